// round 1
// baseline (speedup 1.0000x reference)
#include <cuda_runtime.h>
#include <cstdint>

#define DD 256
#define N_MAX 100000
#define E_MAX 3300000
#define NEG_SLOPE 0.2f

// ---------------- device scratch (no allocations allowed) ----------------
__device__ float g_h2[(size_t)N_MAX * DD];   // h @ W
__device__ float g_h1[(size_t)N_MAX * DD];   // layer-1 output
__device__ float g_ssrc[N_MAX];
__device__ float g_sdst[N_MAX];
__device__ int   g_rowptr[N_MAX + 1];
__device__ int   g_cnt[N_MAX + 1];           // histogram, then cursor
__device__ int   g_edst[E_MAX];

// ---------------- CSR build ----------------
__global__ void zero_cnt_kernel(int n) {
    int i = blockIdx.x * blockDim.x + threadIdx.x;
    if (i <= n) g_cnt[i] = 0;
}

__global__ void hist_kernel(const int* __restrict__ src, int E) {
    int i = blockIdx.x * blockDim.x + threadIdx.x;
    if (i < E) atomicAdd(&g_cnt[src[i]], 1);
}

// one block, 1024 threads: exclusive scan of g_cnt[0..N) -> g_rowptr, cursor init
__global__ void scan_kernel(int N, int E) {
    __shared__ int sums[1024];
    int t = threadIdx.x;
    int C = (N + 1023) / 1024;
    int beg = t * C;
    int end = min(beg + C, N);
    int s = 0;
    for (int i = beg; i < end; ++i) s += g_cnt[i];
    sums[t] = s;
    __syncthreads();
    // Hillis-Steele inclusive scan
    for (int off = 1; off < 1024; off <<= 1) {
        int v = (t >= off) ? sums[t - off] : 0;
        __syncthreads();
        sums[t] += v;
        __syncthreads();
    }
    int run = (t == 0) ? 0 : sums[t - 1];
    for (int i = beg; i < end; ++i) {
        int c = g_cnt[i];
        g_rowptr[i] = run;
        g_cnt[i] = run;      // cursor for scatter
        run += c;
    }
    if (t == 1023) g_rowptr[N] = E;
}

__global__ void scatter_kernel(const int* __restrict__ src,
                               const int* __restrict__ dst, int E) {
    int i = blockIdx.x * blockDim.x + threadIdx.x;
    if (i < E) {
        int s = src[i];
        int p = atomicAdd(&g_cnt[s], 1);
        g_edst[p] = dst[i];
    }
}

// ---------------- fp32 sgemm: C[M,256] = A[M,256] @ B[256,256] ----------------
__global__ __launch_bounds__(256)
void sgemm_kernel(const float* __restrict__ A, const float* __restrict__ B,
                  float* __restrict__ C, int M) {
    const int BM = 128, BN = 128, BK = 8, TM = 8, TN = 8;
    __shared__ float As[BK][BM];
    __shared__ float Bs[BK][BN];

    int tid = threadIdx.x;
    int crow = blockIdx.y * BM;
    int ccol = blockIdx.x * BN;
    int ty = tid / 16;          // 0..15
    int tx = tid % 16;          // 0..15

    float acc[TM][TN];
#pragma unroll
    for (int i = 0; i < TM; ++i)
#pragma unroll
        for (int j = 0; j < TN; ++j) acc[i][j] = 0.f;

    int a_r = tid >> 1;            // 0..127
    int a_c = (tid & 1) * 4;       // 0 or 4
    int b_r = tid >> 5;            // 0..7
    int b_c = (tid & 31) * 4;      // 0..124

    for (int k0 = 0; k0 < DD; k0 += BK) {
        float4 av;
        int arow = crow + a_r;
        if (arow < M) av = *(const float4*)(A + (size_t)arow * DD + k0 + a_c);
        else          av = make_float4(0.f, 0.f, 0.f, 0.f);
        As[a_c + 0][a_r] = av.x;
        As[a_c + 1][a_r] = av.y;
        As[a_c + 2][a_r] = av.z;
        As[a_c + 3][a_r] = av.w;

        float4 bv = *(const float4*)(B + (size_t)(k0 + b_r) * DD + ccol + b_c);
        *(float4*)&Bs[b_r][b_c] = bv;
        __syncthreads();

#pragma unroll
        for (int k = 0; k < BK; ++k) {
            float ra[TM], rb[TN];
#pragma unroll
            for (int i = 0; i < TM; ++i) ra[i] = As[k][ty * TM + i];
#pragma unroll
            for (int j = 0; j < TN; ++j) rb[j] = Bs[k][tx * TN + j];
#pragma unroll
            for (int i = 0; i < TM; ++i)
#pragma unroll
                for (int j = 0; j < TN; ++j) acc[i][j] += ra[i] * rb[j];
        }
        __syncthreads();
    }

#pragma unroll
    for (int i = 0; i < TM; ++i) {
        int row = crow + ty * TM + i;
        if (row >= M) continue;
        float* cp = C + (size_t)row * DD + ccol + tx * TN;
        *(float4*)(cp + 0) = make_float4(acc[i][0], acc[i][1], acc[i][2], acc[i][3]);
        *(float4*)(cp + 4) = make_float4(acc[i][4], acc[i][5], acc[i][6], acc[i][7]);
    }
}

// ---------------- per-node score dots: ssrc = h2 . a[:256], sdst = h2 . a[256:] ----------------
__global__ void dots_kernel(const float* __restrict__ h2, const float* __restrict__ a,
                            int N) {
    int warp = (blockIdx.x * blockDim.x + threadIdx.x) >> 5;
    if (warp >= N) return;
    int lane = threadIdx.x & 31;
    const float4* row = (const float4*)(h2 + (size_t)warp * DD);
    const float4* a0 = (const float4*)a;
    const float4* a1 = (const float4*)(a + DD);
    float d0 = 0.f, d1 = 0.f;
#pragma unroll
    for (int j = 0; j < 2; ++j) {
        float4 v = row[lane + 32 * j];
        float4 x = a0[lane + 32 * j];
        float4 y = a1[lane + 32 * j];
        d0 += v.x * x.x + v.y * x.y + v.z * x.z + v.w * x.w;
        d1 += v.x * y.x + v.y * y.y + v.z * y.z + v.w * y.w;
    }
#pragma unroll
    for (int off = 16; off > 0; off >>= 1) {
        d0 += __shfl_xor_sync(0xffffffffu, d0, off);
        d1 += __shfl_xor_sync(0xffffffffu, d1, off);
    }
    if (lane == 0) {
        g_ssrc[warp] = d0;
        g_sdst[warp] = d1;
    }
}

// ---------------- aggregation: one warp per node, register accumulators ----------------
__global__ __launch_bounds__(256)
void aggregate_kernel(const float* __restrict__ h2, float* __restrict__ out, int N) {
    int warp = (blockIdx.x * blockDim.x + threadIdx.x) >> 5;
    if (warp >= N) return;
    int lane = threadIdx.x & 31;

    float4 acc0 = make_float4(0.f, 0.f, 0.f, 0.f);
    float4 acc1 = make_float4(0.f, 0.f, 0.f, 0.f);
    float dsum = 0.f;
    float ss = g_ssrc[warp];

    int beg = g_rowptr[warp];
    int end = g_rowptr[warp + 1];
    for (int i = beg; i < end; ++i) {
        int d = g_edst[i];
        float sc = ss + g_sdst[d];
        float l = sc > 0.f ? sc : NEG_SLOPE * sc;
        float e = __expf(-l);
        dsum += e;
        const float4* row = (const float4*)(h2 + (size_t)d * DD);
        float4 v0 = row[lane * 2 + 0];
        float4 v1 = row[lane * 2 + 1];
        acc0.x += e * v0.x; acc0.y += e * v0.y; acc0.z += e * v0.z; acc0.w += e * v0.w;
        acc1.x += e * v1.x; acc1.y += e * v1.y; acc1.z += e * v1.z; acc1.w += e * v1.w;
    }
    float inv = 1.f / dsum;
    float r[8] = {acc0.x * inv, acc0.y * inv, acc0.z * inv, acc0.w * inv,
                  acc1.x * inv, acc1.y * inv, acc1.z * inv, acc1.w * inv};
#pragma unroll
    for (int j = 0; j < 8; ++j) r[j] = r[j] > 0.f ? r[j] : (__expf(r[j]) - 1.f);

    float4* op = (float4*)(out + (size_t)warp * DD);
    op[lane * 2 + 0] = make_float4(r[0], r[1], r[2], r[3]);
    op[lane * 2 + 1] = make_float4(r[4], r[5], r[6], r[7]);
}

// ---------------- launch ----------------
static void run_layer(const float* h_in, const float* W, const float* a,
                      float* h2, float* out, int N) {
    dim3 ggrid(DD / 128, (N + 127) / 128);
    sgemm_kernel<<<ggrid, 256>>>(h_in, W, h2, N);
    int dot_blocks = (N * 32 + 255) / 256;
    dots_kernel<<<dot_blocks, 256>>>(h2, a, N);
    int agg_blocks = (N * 32 + 255) / 256;
    aggregate_kernel<<<agg_blocks, 256>>>(h2, out, N);
}

extern "C" void kernel_launch(void* const* d_in, const int* in_sizes, int n_in,
                              void* d_out, int out_size) {
    const float* emb = (const float*)d_in[0];
    const float* W1  = (const float*)d_in[1];
    const float* a1  = (const float*)d_in[2];
    const float* W2  = (const float*)d_in[3];
    const float* a2  = (const float*)d_in[4];
    const int* edges = (const int*)d_in[5];

    int N = in_sizes[0] / DD;
    int E = in_sizes[5] / 2;
    const int* src = edges;
    const int* dst = edges + E;

    // CSR build (shared by both layers)
    zero_cnt_kernel<<<(N + 256) / 256, 256>>>(N);
    hist_kernel<<<(E + 255) / 256, 256>>>(src, E);
    scan_kernel<<<1, 1024>>>(N, E);
    scatter_kernel<<<(E + 255) / 256, 256>>>(src, dst, E);

    float* h2 = nullptr; float* h1 = nullptr;
    cudaGetSymbolAddress((void**)&h2, g_h2);
    cudaGetSymbolAddress((void**)&h1, g_h1);

    // layer 1: emb -> h1
    run_layer(emb, W1, a1, h2, h1, N);
    // layer 2: h1 -> d_out
    run_layer(h1, W2, a2, h2, (float*)d_out, N);
}

// round 3
// speedup vs baseline: 1.2357x; 1.2357x over previous
#include <cuda_runtime.h>
#include <cuda_bf16.h>
#include <cstdint>

#define DD 256
#define N_MAX 100000
#define E_MAX 3300000
#define NEG_SLOPE 0.2f

// ======================= device scratch =======================
__device__ float g_h2[(size_t)N_MAX * DD];
__device__ float g_h1[(size_t)N_MAX * DD];
__device__ float g_ssrc[N_MAX];
__device__ float g_sdst[N_MAX];
__device__ int   g_rowptr[N_MAX + 1];
__device__ int   g_cnt[N_MAX + 1];
__device__ int   g_edst[E_MAX];
__device__ __nv_bfloat16 g_wt_hi[DD * DD];   // W^T hi  [n][k]
__device__ __nv_bfloat16 g_wt_lo[DD * DD];   // W^T lo  [n][k]

// ======================= helpers =======================
__device__ __forceinline__ uint32_t smem_u32(const void* p) {
    uint32_t a;
    asm("{ .reg .u64 t; cvta.to.shared.u64 t, %1; cvt.u32.u64 %0, t; }"
        : "=r"(a) : "l"(p));
    return a;
}

__device__ __forceinline__ uint32_t bf2pack(__nv_bfloat16 a, __nv_bfloat16 b) {
    __nv_bfloat162 t(a, b);
    return *reinterpret_cast<uint32_t*>(&t);
}

#define LDSM_X4(r, addr) \
    asm volatile("ldmatrix.sync.aligned.m8n8.x4.shared.b16 {%0,%1,%2,%3}, [%4];" \
        : "=r"((r)[0]), "=r"((r)[1]), "=r"((r)[2]), "=r"((r)[3]) : "r"(addr))

#define MMA_BF16(d, a, b0, b1) \
    asm volatile("mma.sync.aligned.m16n8k16.row.col.f32.bf16.bf16.f32 " \
        "{%0,%1,%2,%3},{%4,%5,%6,%7},{%8,%9},{%0,%1,%2,%3};" \
        : "+f"((d)[0]), "+f"((d)[1]), "+f"((d)[2]), "+f"((d)[3]) \
        : "r"((a)[0]), "r"((a)[1]), "r"((a)[2]), "r"((a)[3]), "r"(b0), "r"(b1))

// ======================= CSR build =======================
__global__ void zero_cnt_kernel(int n) {
    int i = blockIdx.x * blockDim.x + threadIdx.x;
    if (i <= n) g_cnt[i] = 0;
}

__global__ void hist_kernel(const int* __restrict__ src, int E) {
    int i = blockIdx.x * blockDim.x + threadIdx.x;
    if (i < E) atomicAdd(&g_cnt[src[i]], 1);
}

__global__ void scan_kernel(int N, int E) {
    __shared__ int sums[1024];
    int t = threadIdx.x;
    int C = (N + 1023) / 1024;
    int beg = t * C;
    int end = min(beg + C, N);
    int s = 0;
    for (int i = beg; i < end; ++i) s += g_cnt[i];
    sums[t] = s;
    __syncthreads();
    for (int off = 1; off < 1024; off <<= 1) {
        int v = (t >= off) ? sums[t - off] : 0;
        __syncthreads();
        sums[t] += v;
        __syncthreads();
    }
    int run = (t == 0) ? 0 : sums[t - 1];
    for (int i = beg; i < end; ++i) {
        int c = g_cnt[i];
        g_rowptr[i] = run;
        g_cnt[i] = run;
        run += c;
    }
    if (t == 1023) g_rowptr[N] = E;
}

__global__ void scatter_kernel(const int* __restrict__ src,
                               const int* __restrict__ dst, int E) {
    int i = blockIdx.x * blockDim.x + threadIdx.x;
    if (i < E) {
        int s = src[i];
        int p = atomicAdd(&g_cnt[s], 1);
        g_edst[p] = dst[i];
    }
}

// ======================= W split+transpose: Wt_hi/lo[n][k] = split(W[k][n]) =======================
__global__ void split_w_kernel(const float* __restrict__ W) {
    int idx = blockIdx.x * blockDim.x + threadIdx.x;
    if (idx >= DD * DD) return;
    int k = idx >> 8;
    int n = idx & 255;
    float v = W[k * DD + n];
    __nv_bfloat16 h = __float2bfloat16_rn(v);
    __nv_bfloat16 l = __float2bfloat16_rn(v - __bfloat162float(h));
    g_wt_hi[n * DD + k] = h;
    g_wt_lo[n * DD + k] = l;
}

// ======================= bf16x3 mma.sync GEMM: C[M,256] = A[M,256] @ W =======================
// CTA tile 128x128, BK=32, 8 warps in 2(M)x4(N), warp tile 64x32.
#define SPITCH 40   // bf16 elems per smem row (80B) -> conflict-free ldmatrix

__global__ __launch_bounds__(256, 1)
void gemm_mma_kernel(const float* __restrict__ A, float* __restrict__ C, int M) {
    __shared__ __nv_bfloat16 sA_hi[128 * SPITCH];
    __shared__ __nv_bfloat16 sA_lo[128 * SPITCH];
    __shared__ __nv_bfloat16 sB_hi[128 * SPITCH];
    __shared__ __nv_bfloat16 sB_lo[128 * SPITCH];

    const int tid = threadIdx.x;
    const int wid = tid >> 5;
    const int lane = tid & 31;
    const int wm = wid >> 2;          // 0..1 -> warp row tile of 64
    const int wn = wid & 3;           // 0..3 -> warp col tile of 32
    const int crow = blockIdx.y * 128;
    const int ccol = blockIdx.x * 128;

    const uint32_t sa_hi = smem_u32(sA_hi);
    const uint32_t sa_lo = smem_u32(sA_lo);
    const uint32_t sb_hi = smem_u32(sB_hi);
    const uint32_t sb_lo = smem_u32(sB_lo);

    float acc[4][4][4];
#pragma unroll
    for (int i = 0; i < 4; ++i)
#pragma unroll
        for (int j = 0; j < 4; ++j)
#pragma unroll
            for (int k = 0; k < 4; ++k) acc[i][j][k] = 0.f;

    // ldmatrix source addresses (per-lane)
    const int lrow = lane & 15;
    const int lcol8 = (lane >> 4) << 3;   // 0 or 8

    for (int it = 0; it < DD / 32; ++it) {
        const int k0 = it * 32;

        // ---- fill A tile: 128 rows x 32 cols, split fp32 -> hi/lo bf16 ----
#pragma unroll
        for (int i = 0; i < 4; ++i) {
            int idx = tid + i * 256;        // 0..1023 float4 slots
            int row = idx >> 3;             // 8 float4 per row
            int c4 = idx & 7;
            float4 v;
            if (crow + row < M)
                v = *(const float4*)(A + (size_t)(crow + row) * DD + k0 + c4 * 4);
            else
                v = make_float4(0.f, 0.f, 0.f, 0.f);
            __nv_bfloat16 hx = __float2bfloat16_rn(v.x);
            __nv_bfloat16 hy = __float2bfloat16_rn(v.y);
            __nv_bfloat16 hz = __float2bfloat16_rn(v.z);
            __nv_bfloat16 hw = __float2bfloat16_rn(v.w);
            uint32_t h01 = bf2pack(hx, hy);
            uint32_t h23 = bf2pack(hz, hw);
            uint32_t l01 = bf2pack(__float2bfloat16_rn(v.x - __bfloat162float(hx)),
                                   __float2bfloat16_rn(v.y - __bfloat162float(hy)));
            uint32_t l23 = bf2pack(__float2bfloat16_rn(v.z - __bfloat162float(hz)),
                                   __float2bfloat16_rn(v.w - __bfloat162float(hw)));
            int off = row * SPITCH + c4 * 4;
            *(uint2*)(sA_hi + off) = make_uint2(h01, h23);
            *(uint2*)(sA_lo + off) = make_uint2(l01, l23);
        }

        // ---- fill B tile from pre-split Wt[n][k]: 128 rows(n) x 32 cols(k) ----
#pragma unroll
        for (int i = 0; i < 2; ++i) {
            int idx = tid + i * 256;        // 0..511 uint4(16B) slots
            int row = idx >> 2;             // 4x16B per row (64B)
            int q = idx & 3;
            const uint4* gh = (const uint4*)(g_wt_hi + (size_t)(ccol + row) * DD + k0 + q * 8);
            const uint4* gl = (const uint4*)(g_wt_lo + (size_t)(ccol + row) * DD + k0 + q * 8);
            int off = row * SPITCH + q * 8;
            *(uint4*)(sB_hi + off) = *gh;
            *(uint4*)(sB_lo + off) = *gl;
        }
        __syncthreads();

        // ---- mma over this k-chunk ----
#pragma unroll
        for (int kk = 0; kk < 32; kk += 16) {
            uint32_t ah[4][4], al[4][4];
#pragma unroll
            for (int mt = 0; mt < 4; ++mt) {
                int row = wm * 64 + mt * 16 + lrow;
                uint32_t boff = (uint32_t)(row * SPITCH + kk + lcol8) * 2;
                LDSM_X4(ah[mt], sa_hi + boff);
                LDSM_X4(al[mt], sa_lo + boff);
            }
            uint32_t bh[2][4], bl[2][4];
#pragma unroll
            for (int nb = 0; nb < 2; ++nb) {
                int row = wn * 32 + nb * 16 + lrow;
                uint32_t boff = (uint32_t)(row * SPITCH + kk + lcol8) * 2;
                LDSM_X4(bh[nb], sb_hi + boff);
                LDSM_X4(bl[nb], sb_lo + boff);
            }
#pragma unroll
            for (int mt = 0; mt < 4; ++mt) {
#pragma unroll
                for (int nt = 0; nt < 4; ++nt) {
                    int nb = nt >> 1;
                    int hh = nt & 1;
                    uint32_t b0h = bh[nb][hh], b1h = bh[nb][2 + hh];
                    uint32_t b0l = bl[nb][hh], b1l = bl[nb][2 + hh];
                    MMA_BF16(acc[mt][nt], ah[mt], b0h, b1h);
                    MMA_BF16(acc[mt][nt], ah[mt], b0l, b1l);
                    MMA_BF16(acc[mt][nt], al[mt], b0h, b1h);
                }
            }
        }
        __syncthreads();
    }

    // ---- epilogue ----
    const int tq = lane >> 2;     // 0..7
    const int tr = lane & 3;      // 0..3
#pragma unroll
    for (int mt = 0; mt < 4; ++mt) {
#pragma unroll
        for (int nt = 0; nt < 4; ++nt) {
            int row0 = crow + wm * 64 + mt * 16 + tq;
            int col = ccol + wn * 32 + nt * 8 + tr * 2;
            if (row0 < M)
                *(float2*)(C + (size_t)row0 * DD + col) =
                    make_float2(acc[mt][nt][0], acc[mt][nt][1]);
            int row1 = row0 + 8;
            if (row1 < M)
                *(float2*)(C + (size_t)row1 * DD + col) =
                    make_float2(acc[mt][nt][2], acc[mt][nt][3]);
        }
    }
}

// ======================= per-node score dots =======================
__global__ void dots_kernel(const float* __restrict__ h2, const float* __restrict__ a,
                            int N) {
    int warp = (blockIdx.x * blockDim.x + threadIdx.x) >> 5;
    if (warp >= N) return;
    int lane = threadIdx.x & 31;
    const float4* row = (const float4*)(h2 + (size_t)warp * DD);
    const float4* a0 = (const float4*)a;
    const float4* a1 = (const float4*)(a + DD);
    float d0 = 0.f, d1 = 0.f;
#pragma unroll
    for (int j = 0; j < 2; ++j) {
        float4 v = row[lane + 32 * j];
        float4 x = a0[lane + 32 * j];
        float4 y = a1[lane + 32 * j];
        d0 += v.x * x.x + v.y * x.y + v.z * x.z + v.w * x.w;
        d1 += v.x * y.x + v.y * y.y + v.z * y.z + v.w * y.w;
    }
#pragma unroll
    for (int off = 16; off > 0; off >>= 1) {
        d0 += __shfl_xor_sync(0xffffffffu, d0, off);
        d1 += __shfl_xor_sync(0xffffffffu, d1, off);
    }
    if (lane == 0) {
        g_ssrc[warp] = d0;
        g_sdst[warp] = d1;
    }
}

// ======================= aggregation: one warp per node =======================
__global__ __launch_bounds__(256)
void aggregate_kernel(const float* __restrict__ h2, float* __restrict__ out, int N) {
    int warp = (blockIdx.x * blockDim.x + threadIdx.x) >> 5;
    if (warp >= N) return;
    int lane = threadIdx.x & 31;

    float4 acc0 = make_float4(0.f, 0.f, 0.f, 0.f);
    float4 acc1 = make_float4(0.f, 0.f, 0.f, 0.f);
    float dsum = 0.f;
    float ss = g_ssrc[warp];

    int beg = g_rowptr[warp];
    int end = g_rowptr[warp + 1];
    for (int i = beg; i < end; ++i) {
        int d = g_edst[i];
        float sc = ss + g_sdst[d];
        float l = sc > 0.f ? sc : NEG_SLOPE * sc;
        float e = __expf(-l);
        dsum += e;
        const float4* row = (const float4*)(h2 + (size_t)d * DD);
        float4 v0 = row[lane * 2 + 0];
        float4 v1 = row[lane * 2 + 1];
        acc0.x += e * v0.x; acc0.y += e * v0.y; acc0.z += e * v0.z; acc0.w += e * v0.w;
        acc1.x += e * v1.x; acc1.y += e * v1.y; acc1.z += e * v1.z; acc1.w += e * v1.w;
    }
    float inv = 1.f / dsum;
    float r[8] = {acc0.x * inv, acc0.y * inv, acc0.z * inv, acc0.w * inv,
                  acc1.x * inv, acc1.y * inv, acc1.z * inv, acc1.w * inv};
#pragma unroll
    for (int j = 0; j < 8; ++j) r[j] = r[j] > 0.f ? r[j] : (__expf(r[j]) - 1.f);

    float4* op = (float4*)(out + (size_t)warp * DD);
    op[lane * 2 + 0] = make_float4(r[0], r[1], r[2], r[3]);
    op[lane * 2 + 1] = make_float4(r[4], r[5], r[6], r[7]);
}

// ======================= launch =======================
static void run_layer(const float* h_in, const float* W, const float* a,
                      float* h2, float* out, int N) {
    split_w_kernel<<<(DD * DD + 255) / 256, 256>>>(W);
    dim3 ggrid(DD / 128, (N + 127) / 128);
    gemm_mma_kernel<<<ggrid, 256>>>(h_in, h2, N);
    int dot_blocks = (N * 32 + 255) / 256;
    dots_kernel<<<dot_blocks, 256>>>(h2, a, N);
    int agg_blocks = (N * 32 + 255) / 256;
    aggregate_kernel<<<agg_blocks, 256>>>(h2, out, N);
}

extern "C" void kernel_launch(void* const* d_in, const int* in_sizes, int n_in,
                              void* d_out, int out_size) {
    const float* emb = (const float*)d_in[0];
    const float* W1  = (const float*)d_in[1];
    const float* a1  = (const float*)d_in[2];
    const float* W2  = (const float*)d_in[3];
    const float* a2  = (const float*)d_in[4];
    const int* edges = (const int*)d_in[5];

    int N = in_sizes[0] / DD;
    int E = in_sizes[5] / 2;
    const int* src = edges;
    const int* dst = edges + E;

    // CSR build (shared by both layers)
    zero_cnt_kernel<<<(N + 256) / 256, 256>>>(N);
    hist_kernel<<<(E + 255) / 256, 256>>>(src, E);
    scan_kernel<<<1, 1024>>>(N, E);
    scatter_kernel<<<(E + 255) / 256, 256>>>(src, dst, E);

    float* h2 = nullptr; float* h1 = nullptr;
    cudaGetSymbolAddress((void**)&h2, g_h2);
    cudaGetSymbolAddress((void**)&h1, g_h1);

    run_layer(emb, W1, a1, h2, h1, N);
    run_layer(h1, W2, a2, h2, (float*)d_out, N);
}

// round 6
// speedup vs baseline: 1.4808x; 1.1984x over previous
#include <cuda_runtime.h>
#include <cuda_bf16.h>
#include <cuda_fp16.h>
#include <cstdint>

#define DD 256
#define N_MAX 100000
#define E_MAX 3300000
#define NEG_SLOPE 0.2f

// ======================= device scratch =======================
__device__ float g_h2[(size_t)N_MAX * DD];
__device__ float g_h1[(size_t)N_MAX * DD];
__device__ __half g_h2h[(size_t)N_MAX * DD];   // fp16 copy for aggregation
__device__ float g_ssrc[N_MAX];
__device__ float g_sdst[N_MAX];
__device__ int   g_rowptr[N_MAX + 1];
__device__ int   g_cnt[N_MAX + 1];
__device__ int   g_edst[E_MAX];
__device__ __nv_bfloat16 g_wt_hi[DD * DD];   // W^T hi  [n][k]
__device__ __nv_bfloat16 g_wt_lo[DD * DD];   // W^T lo  [n][k]

// ======================= helpers =======================
__device__ __forceinline__ uint32_t smem_u32(const void* p) {
    uint32_t a;
    asm("{ .reg .u64 t; cvta.to.shared.u64 t, %1; cvt.u32.u64 %0, t; }"
        : "=r"(a) : "l"(p));
    return a;
}

__device__ __forceinline__ uint32_t bf2pack(__nv_bfloat16 a, __nv_bfloat16 b) {
    __nv_bfloat162 t(a, b);
    return *reinterpret_cast<uint32_t*>(&t);
}

#define LDSM_X4(r, addr) \
    asm volatile("ldmatrix.sync.aligned.m8n8.x4.shared.b16 {%0,%1,%2,%3}, [%4];" \
        : "=r"((r)[0]), "=r"((r)[1]), "=r"((r)[2]), "=r"((r)[3]) : "r"(addr))

#define MMA_BF16(d, a, b0, b1) \
    asm volatile("mma.sync.aligned.m16n8k16.row.col.f32.bf16.bf16.f32 " \
        "{%0,%1,%2,%3},{%4,%5,%6,%7},{%8,%9},{%0,%1,%2,%3};" \
        : "+f"((d)[0]), "+f"((d)[1]), "+f"((d)[2]), "+f"((d)[3]) \
        : "r"((a)[0]), "r"((a)[1]), "r"((a)[2]), "r"((a)[3]), "r"(b0), "r"(b1))

// ======================= CSR build =======================
__global__ void zero_cnt_kernel(int n) {
    int i = blockIdx.x * blockDim.x + threadIdx.x;
    if (i <= n) g_cnt[i] = 0;
}

__global__ void hist_kernel(const int* __restrict__ src, int E) {
    int i = blockIdx.x * blockDim.x + threadIdx.x;
    if (i < E) atomicAdd(&g_cnt[src[i]], 1);
}

__global__ void scan_kernel(int N, int E) {
    __shared__ int sums[1024];
    int t = threadIdx.x;
    int C = (N + 1023) / 1024;
    int beg = t * C;
    int end = min(beg + C, N);
    int s = 0;
    for (int i = beg; i < end; ++i) s += g_cnt[i];
    sums[t] = s;
    __syncthreads();
    for (int off = 1; off < 1024; off <<= 1) {
        int v = (t >= off) ? sums[t - off] : 0;
        __syncthreads();
        sums[t] += v;
        __syncthreads();
    }
    int run = (t == 0) ? 0 : sums[t - 1];
    for (int i = beg; i < end; ++i) {
        int c = g_cnt[i];
        g_rowptr[i] = run;
        g_cnt[i] = run;
        run += c;
    }
    if (t == 1023) g_rowptr[N] = E;
}

__global__ void scatter_kernel(const int* __restrict__ src,
                               const int* __restrict__ dst, int E) {
    int i = blockIdx.x * blockDim.x + threadIdx.x;
    if (i < E) {
        int s = src[i];
        int p = atomicAdd(&g_cnt[s], 1);
        g_edst[p] = dst[i];
    }
}

// ======================= W split+transpose =======================
__global__ void split_w_kernel(const float* __restrict__ W) {
    int idx = blockIdx.x * blockDim.x + threadIdx.x;
    if (idx >= DD * DD) return;
    int k = idx >> 8;
    int n = idx & 255;
    float v = W[k * DD + n];
    __nv_bfloat16 h = __float2bfloat16_rn(v);
    __nv_bfloat16 l = __float2bfloat16_rn(v - __bfloat162float(h));
    g_wt_hi[n * DD + k] = h;
    g_wt_lo[n * DD + k] = l;
}

// ======================= bf16x3 mma.sync GEMM =======================
#define SPITCH 40   // bf16 elems per smem row (80B) -> conflict-free ldmatrix

__global__ __launch_bounds__(256, 1)
void gemm_mma_kernel(const float* __restrict__ A, float* __restrict__ C,
                     __half* __restrict__ Ch, int M) {
    __shared__ __nv_bfloat16 sA_hi[128 * SPITCH];
    __shared__ __nv_bfloat16 sA_lo[128 * SPITCH];
    __shared__ __nv_bfloat16 sB_hi[128 * SPITCH];
    __shared__ __nv_bfloat16 sB_lo[128 * SPITCH];

    const int tid = threadIdx.x;
    const int wid = tid >> 5;
    const int lane = tid & 31;
    const int wm = wid >> 2;
    const int wn = wid & 3;
    const int crow = blockIdx.y * 128;
    const int ccol = blockIdx.x * 128;

    const uint32_t sa_hi = smem_u32(sA_hi);
    const uint32_t sa_lo = smem_u32(sA_lo);
    const uint32_t sb_hi = smem_u32(sB_hi);
    const uint32_t sb_lo = smem_u32(sB_lo);

    float acc[4][4][4];
#pragma unroll
    for (int i = 0; i < 4; ++i)
#pragma unroll
        for (int j = 0; j < 4; ++j)
#pragma unroll
            for (int k = 0; k < 4; ++k) acc[i][j][k] = 0.f;

    const int lrow = lane & 15;
    const int lcol8 = (lane >> 4) << 3;

    for (int it = 0; it < DD / 32; ++it) {
        const int k0 = it * 32;

#pragma unroll
        for (int i = 0; i < 4; ++i) {
            int idx = tid + i * 256;
            int row = idx >> 3;
            int c4 = idx & 7;
            float4 v;
            if (crow + row < M)
                v = *(const float4*)(A + (size_t)(crow + row) * DD + k0 + c4 * 4);
            else
                v = make_float4(0.f, 0.f, 0.f, 0.f);
            __nv_bfloat16 hx = __float2bfloat16_rn(v.x);
            __nv_bfloat16 hy = __float2bfloat16_rn(v.y);
            __nv_bfloat16 hz = __float2bfloat16_rn(v.z);
            __nv_bfloat16 hw = __float2bfloat16_rn(v.w);
            uint32_t h01 = bf2pack(hx, hy);
            uint32_t h23 = bf2pack(hz, hw);
            uint32_t l01 = bf2pack(__float2bfloat16_rn(v.x - __bfloat162float(hx)),
                                   __float2bfloat16_rn(v.y - __bfloat162float(hy)));
            uint32_t l23 = bf2pack(__float2bfloat16_rn(v.z - __bfloat162float(hz)),
                                   __float2bfloat16_rn(v.w - __bfloat162float(hw)));
            int off = row * SPITCH + c4 * 4;
            *(uint2*)(sA_hi + off) = make_uint2(h01, h23);
            *(uint2*)(sA_lo + off) = make_uint2(l01, l23);
        }

#pragma unroll
        for (int i = 0; i < 2; ++i) {
            int idx = tid + i * 256;
            int row = idx >> 2;
            int q = idx & 3;
            const uint4* gh = (const uint4*)(g_wt_hi + (size_t)(ccol + row) * DD + k0 + q * 8);
            const uint4* gl = (const uint4*)(g_wt_lo + (size_t)(ccol + row) * DD + k0 + q * 8);
            int off = row * SPITCH + q * 8;
            *(uint4*)(sB_hi + off) = *gh;
            *(uint4*)(sB_lo + off) = *gl;
        }
        __syncthreads();

#pragma unroll
        for (int kk = 0; kk < 32; kk += 16) {
            uint32_t ah[4][4], al[4][4];
#pragma unroll
            for (int mt = 0; mt < 4; ++mt) {
                int row = wm * 64 + mt * 16 + lrow;
                uint32_t boff = (uint32_t)(row * SPITCH + kk + lcol8) * 2;
                LDSM_X4(ah[mt], sa_hi + boff);
                LDSM_X4(al[mt], sa_lo + boff);
            }
            uint32_t bh[2][4], bl[2][4];
#pragma unroll
            for (int nb = 0; nb < 2; ++nb) {
                int row = wn * 32 + nb * 16 + lrow;
                uint32_t boff = (uint32_t)(row * SPITCH + kk + lcol8) * 2;
                LDSM_X4(bh[nb], sb_hi + boff);
                LDSM_X4(bl[nb], sb_lo + boff);
            }
#pragma unroll
            for (int mt = 0; mt < 4; ++mt) {
#pragma unroll
                for (int nt = 0; nt < 4; ++nt) {
                    int nb = nt >> 1;
                    int hh = nt & 1;
                    uint32_t b0h = bh[nb][hh], b1h = bh[nb][2 + hh];
                    uint32_t b0l = bl[nb][hh], b1l = bl[nb][2 + hh];
                    MMA_BF16(acc[mt][nt], ah[mt], b0h, b1h);
                    MMA_BF16(acc[mt][nt], ah[mt], b0l, b1l);
                    MMA_BF16(acc[mt][nt], al[mt], b0h, b1h);
                }
            }
        }
        __syncthreads();
    }

    // ---- epilogue: write fp32 C and fp16 Ch ----
    const int tq = lane >> 2;
    const int tr = lane & 3;
#pragma unroll
    for (int mt = 0; mt < 4; ++mt) {
#pragma unroll
        for (int nt = 0; nt < 4; ++nt) {
            int row0 = crow + wm * 64 + mt * 16 + tq;
            int col = ccol + wn * 32 + nt * 8 + tr * 2;
            if (row0 < M) {
                *(float2*)(C + (size_t)row0 * DD + col) =
                    make_float2(acc[mt][nt][0], acc[mt][nt][1]);
                *(__half2*)(Ch + (size_t)row0 * DD + col) =
                    __floats2half2_rn(acc[mt][nt][0], acc[mt][nt][1]);
            }
            int row1 = row0 + 8;
            if (row1 < M) {
                *(float2*)(C + (size_t)row1 * DD + col) =
                    make_float2(acc[mt][nt][2], acc[mt][nt][3]);
                *(__half2*)(Ch + (size_t)row1 * DD + col) =
                    __floats2half2_rn(acc[mt][nt][2], acc[mt][nt][3]);
            }
        }
    }
}

// ======================= per-node score dots (fp32 h2) =======================
__global__ void dots_kernel(const float* __restrict__ h2, const float* __restrict__ a,
                            int N) {
    int warp = (blockIdx.x * blockDim.x + threadIdx.x) >> 5;
    if (warp >= N) return;
    int lane = threadIdx.x & 31;
    const float4* row = (const float4*)(h2 + (size_t)warp * DD);
    const float4* a0 = (const float4*)a;
    const float4* a1 = (const float4*)(a + DD);
    float d0 = 0.f, d1 = 0.f;
#pragma unroll
    for (int j = 0; j < 2; ++j) {
        float4 v = row[lane + 32 * j];
        float4 x = a0[lane + 32 * j];
        float4 y = a1[lane + 32 * j];
        d0 += v.x * x.x + v.y * x.y + v.z * x.z + v.w * x.w;
        d1 += v.x * y.x + v.y * y.y + v.z * y.z + v.w * y.w;
    }
#pragma unroll
    for (int off = 16; off > 0; off >>= 1) {
        d0 += __shfl_xor_sync(0xffffffffu, d0, off);
        d1 += __shfl_xor_sync(0xffffffffu, d1, off);
    }
    if (lane == 0) {
        g_ssrc[warp] = d0;
        g_sdst[warp] = d1;
    }
}

// ======================= aggregation: one warp per node, fp16 rows =======================
__global__ __launch_bounds__(256)
void aggregate_kernel(const __half* __restrict__ h2h, float* __restrict__ out, int N) {
    int warp = (blockIdx.x * blockDim.x + threadIdx.x) >> 5;
    if (warp >= N) return;
    int lane = threadIdx.x & 31;

    float acc[8] = {0.f, 0.f, 0.f, 0.f, 0.f, 0.f, 0.f, 0.f};
    float dsum = 0.f;
    float ss = g_ssrc[warp];

    int beg = g_rowptr[warp];
    int end = g_rowptr[warp + 1];
#pragma unroll 4
    for (int i = beg; i < end; ++i) {
        int d = g_edst[i];
        float sc = ss + g_sdst[d];
        float l = sc > 0.f ? sc : NEG_SLOPE * sc;
        float e = __expf(-l);
        dsum += e;
        // lane covers dims [lane*8, lane*8+8): one 16B load of 8 halves
        uint4 v = *((const uint4*)(h2h + (size_t)d * DD) + lane);
        float2 f0 = __half22float2(*reinterpret_cast<__half2*>(&v.x));
        float2 f1 = __half22float2(*reinterpret_cast<__half2*>(&v.y));
        float2 f2 = __half22float2(*reinterpret_cast<__half2*>(&v.z));
        float2 f3 = __half22float2(*reinterpret_cast<__half2*>(&v.w));
        acc[0] += e * f0.x; acc[1] += e * f0.y;
        acc[2] += e * f1.x; acc[3] += e * f1.y;
        acc[4] += e * f2.x; acc[5] += e * f2.y;
        acc[6] += e * f3.x; acc[7] += e * f3.y;
    }
    float inv = 1.f / dsum;
    float r[8];
#pragma unroll
    for (int j = 0; j < 8; ++j) {
        float t = acc[j] * inv;
        r[j] = t > 0.f ? t : (__expf(t) - 1.f);
    }
    float4* op = (float4*)(out + (size_t)warp * DD + lane * 8);
    op[0] = make_float4(r[0], r[1], r[2], r[3]);
    op[1] = make_float4(r[4], r[5], r[6], r[7]);
}

// ======================= launch =======================
static void run_layer(const float* h_in, const float* W, const float* a,
                      float* h2, __half* h2h, float* out, int N) {
    split_w_kernel<<<(DD * DD + 255) / 256, 256>>>(W);
    dim3 ggrid(DD / 128, (N + 127) / 128);
    gemm_mma_kernel<<<ggrid, 256>>>(h_in, h2, h2h, N);
    int dot_blocks = (N * 32 + 255) / 256;
    dots_kernel<<<dot_blocks, 256>>>(h2, a, N);
    int agg_blocks = (N * 32 + 255) / 256;
    aggregate_kernel<<<agg_blocks, 256>>>(h2h, out, N);
}

extern "C" void kernel_launch(void* const* d_in, const int* in_sizes, int n_in,
                              void* d_out, int out_size) {
    const float* emb = (const float*)d_in[0];
    const float* W1  = (const float*)d_in[1];
    const float* a1  = (const float*)d_in[2];
    const float* W2  = (const float*)d_in[3];
    const float* a2  = (const float*)d_in[4];
    const int* edges = (const int*)d_in[5];

    int N = in_sizes[0] / DD;
    int E = in_sizes[5] / 2;
    const int* src = edges;
    const int* dst = edges + E;

    // CSR build (shared by both layers)
    zero_cnt_kernel<<<(N + 256) / 256, 256>>>(N);
    hist_kernel<<<(E + 255) / 256, 256>>>(src, E);
    scan_kernel<<<1, 1024>>>(N, E);
    scatter_kernel<<<(E + 255) / 256, 256>>>(src, dst, E);

    float* h2 = nullptr; float* h1 = nullptr; __half* h2h = nullptr;
    cudaGetSymbolAddress((void**)&h2, g_h2);
    cudaGetSymbolAddress((void**)&h1, g_h1);
    cudaGetSymbolAddress((void**)&h2h, g_h2h);

    run_layer(emb, W1, a1, h2, h2h, h1, N);
    run_layer(h1, W2, a2, h2, h2h, (float*)d_out, N);
}

// round 12
// speedup vs baseline: 1.6509x; 1.1149x over previous
#include <cuda_runtime.h>
#include <cuda_bf16.h>
#include <cuda_fp16.h>
#include <cstdint>

#define DD 256
#define N_MAX 100000
#define E_MAX 3300000
#define NEG_SLOPE 0.2f

// ======================= device scratch =======================
__device__ __half g_h2h[(size_t)N_MAX * DD];          // fp16 h2 for aggregation
__device__ __nv_bfloat16 g_ah[(size_t)N_MAX * DD];    // A hi (gemm input)
__device__ __nv_bfloat16 g_al[(size_t)N_MAX * DD];    // A lo
__device__ float g_ssrc[N_MAX];
__device__ float g_sdst[N_MAX];
__device__ int   g_rowptr[N_MAX + 1];
__device__ int   g_cnt[N_MAX + 1];
__device__ int   g_edst[E_MAX];
__device__ __nv_bfloat16 g_wt_hi[DD * DD];   // W^T hi  [n][k]
__device__ __nv_bfloat16 g_wt_lo[DD * DD];   // W^T lo  [n][k]

// ======================= helpers =======================
__device__ __forceinline__ uint32_t smem_u32(const void* p) {
    uint32_t a;
    asm("{ .reg .u64 t; cvta.to.shared.u64 t, %1; cvt.u32.u64 %0, t; }"
        : "=r"(a) : "l"(p));
    return a;
}

__device__ __forceinline__ uint32_t bf2pack(__nv_bfloat16 a, __nv_bfloat16 b) {
    __nv_bfloat162 t(a, b);
    return *reinterpret_cast<uint32_t*>(&t);
}

#define LDSM_X4(r, addr) \
    asm volatile("ldmatrix.sync.aligned.m8n8.x4.shared.b16 {%0,%1,%2,%3}, [%4];" \
        : "=r"((r)[0]), "=r"((r)[1]), "=r"((r)[2]), "=r"((r)[3]) : "r"(addr))

#define MMA_BF16(d, a, b0, b1) \
    asm volatile("mma.sync.aligned.m16n8k16.row.col.f32.bf16.bf16.f32 " \
        "{%0,%1,%2,%3},{%4,%5,%6,%7},{%8,%9},{%0,%1,%2,%3};" \
        : "+f"((d)[0]), "+f"((d)[1]), "+f"((d)[2]), "+f"((d)[3]) \
        : "r"((a)[0]), "r"((a)[1]), "r"((a)[2]), "r"((a)[3]), "r"(b0), "r"(b1))

#define CP_ASYNC16(dst_u32, src_ptr) \
    asm volatile("cp.async.cg.shared.global [%0], [%1], 16;" \
        :: "r"(dst_u32), "l"(src_ptr))
#define CP_COMMIT() asm volatile("cp.async.commit_group;" ::: "memory")
#define CP_WAIT0() asm volatile("cp.async.wait_group 0;" ::: "memory")

// ======================= CSR build =======================
__global__ void zero_cnt_kernel(int n) {
    int i = blockIdx.x * blockDim.x + threadIdx.x;
    if (i <= n) g_cnt[i] = 0;
}

__global__ void hist_kernel(const int* __restrict__ src, int E) {
    int i = blockIdx.x * blockDim.x + threadIdx.x;
    if (i < E) atomicAdd(&g_cnt[src[i]], 1);
}

__global__ void scan_kernel(int N, int E) {
    __shared__ int sums[1024];
    int t = threadIdx.x;
    int C = (N + 1023) / 1024;
    int beg = t * C;
    int end = min(beg + C, N);
    int s = 0;
    for (int i = beg; i < end; ++i) s += g_cnt[i];
    sums[t] = s;
    __syncthreads();
    for (int off = 1; off < 1024; off <<= 1) {
        int v = (t >= off) ? sums[t - off] : 0;
        __syncthreads();
        sums[t] += v;
        __syncthreads();
    }
    int run = (t == 0) ? 0 : sums[t - 1];
    for (int i = beg; i < end; ++i) {
        int c = g_cnt[i];
        g_rowptr[i] = run;
        g_cnt[i] = run;
        run += c;
    }
    if (t == 1023) g_rowptr[N] = E;
}

__global__ void scatter_kernel(const int* __restrict__ src,
                               const int* __restrict__ dst, int E) {
    int i = blockIdx.x * blockDim.x + threadIdx.x;
    if (i < E) {
        int s = src[i];
        int p = atomicAdd(&g_cnt[s], 1);
        g_edst[p] = dst[i];
    }
}

// ======================= operand prep =======================
__global__ void split_w_kernel(const float* __restrict__ W) {
    int idx = blockIdx.x * blockDim.x + threadIdx.x;
    if (idx >= DD * DD) return;
    int k = idx >> 8;
    int n = idx & 255;
    float v = W[k * DD + n];
    __nv_bfloat16 h = __float2bfloat16_rn(v);
    __nv_bfloat16 l = __float2bfloat16_rn(v - __bfloat162float(h));
    g_wt_hi[n * DD + k] = h;
    g_wt_lo[n * DD + k] = l;
}

__global__ void split_a_kernel(const float* __restrict__ X, int nq) {
    int i = blockIdx.x * blockDim.x + threadIdx.x;   // float4 index
    if (i >= nq) return;
    float4 v = ((const float4*)X)[i];
    __nv_bfloat16 hx = __float2bfloat16_rn(v.x);
    __nv_bfloat16 hy = __float2bfloat16_rn(v.y);
    __nv_bfloat16 hz = __float2bfloat16_rn(v.z);
    __nv_bfloat16 hw = __float2bfloat16_rn(v.w);
    uint2 h = make_uint2(bf2pack(hx, hy), bf2pack(hz, hw));
    uint2 l = make_uint2(
        bf2pack(__float2bfloat16_rn(v.x - __bfloat162float(hx)),
                __float2bfloat16_rn(v.y - __bfloat162float(hy))),
        bf2pack(__float2bfloat16_rn(v.z - __bfloat162float(hz)),
                __float2bfloat16_rn(v.w - __bfloat162float(hw))));
    ((uint2*)g_ah)[i] = h;
    ((uint2*)g_al)[i] = l;
}

__global__ void zero_s_kernel(int N) {
    int i = blockIdx.x * blockDim.x + threadIdx.x;
    if (i < N) {
        g_ssrc[i] = 0.f;
        g_sdst[i] = 0.f;
    }
}

// ======================= bf16x3 mma.sync GEMM + fused dots =======================
// CTA tile 128x128, BK=32, 8 warps 2(M)x4(N); cp.async fill, register-staged ldsm.
#define SPITCH 40   // bf16 elems per smem row (80B) -> conflict-free ldmatrix

__global__ __launch_bounds__(256, 1)
void gemm_mma_kernel(const __nv_bfloat16* __restrict__ Ahi,
                     const __nv_bfloat16* __restrict__ Alo,
                     const float* __restrict__ avec,
                     __half* __restrict__ Ch, int M) {
    __shared__ __nv_bfloat16 sA_hi[128 * SPITCH];
    __shared__ __nv_bfloat16 sA_lo[128 * SPITCH];
    __shared__ __nv_bfloat16 sB_hi[128 * SPITCH];
    __shared__ __nv_bfloat16 sB_lo[128 * SPITCH];
    __shared__ float s_av[128], s_av2[128];

    const int tid = threadIdx.x;
    const int wid = tid >> 5;
    const int lane = tid & 31;
    const int wm = wid >> 2;
    const int wn = wid & 3;
    const int crow = blockIdx.y * 128;
    const int ccol = blockIdx.x * 128;

    const uint32_t sa_hi = smem_u32(sA_hi);
    const uint32_t sa_lo = smem_u32(sA_lo);
    const uint32_t sb_hi = smem_u32(sB_hi);
    const uint32_t sb_lo = smem_u32(sB_lo);

    if (tid < 128) {
        s_av[tid] = avec[ccol + tid];
        s_av2[tid] = avec[DD + ccol + tid];
    }

    float acc[4][4][4];
#pragma unroll
    for (int i = 0; i < 4; ++i)
#pragma unroll
        for (int j = 0; j < 4; ++j)
#pragma unroll
            for (int k = 0; k < 4; ++k) acc[i][j][k] = 0.f;

    const int lrow = lane & 15;
    const int lcol8 = (lane >> 4) << 3;

    // per-thread cp.async slots: A/B each 512 x 16B slots, 2 per thread
    const int slot0 = tid, slot1 = tid + 256;
    const int ar0 = slot0 >> 2, ac0 = (slot0 & 3) * 8;
    const int ar1 = slot1 >> 2, ac1 = (slot1 & 3) * 8;
    const int agr0 = min(crow + ar0, M - 1);
    const int agr1 = min(crow + ar1, M - 1);

    auto load_tile = [&](int it) {
        const int k0 = it * 32;
        CP_ASYNC16(sa_hi + (uint32_t)(ar0 * SPITCH + ac0) * 2,
                   Ahi + (size_t)agr0 * DD + k0 + ac0);
        CP_ASYNC16(sa_hi + (uint32_t)(ar1 * SPITCH + ac1) * 2,
                   Ahi + (size_t)agr1 * DD + k0 + ac1);
        CP_ASYNC16(sa_lo + (uint32_t)(ar0 * SPITCH + ac0) * 2,
                   Alo + (size_t)agr0 * DD + k0 + ac0);
        CP_ASYNC16(sa_lo + (uint32_t)(ar1 * SPITCH + ac1) * 2,
                   Alo + (size_t)agr1 * DD + k0 + ac1);
        CP_ASYNC16(sb_hi + (uint32_t)(ar0 * SPITCH + ac0) * 2,
                   g_wt_hi + (size_t)(ccol + ar0) * DD + k0 + ac0);
        CP_ASYNC16(sb_hi + (uint32_t)(ar1 * SPITCH + ac1) * 2,
                   g_wt_hi + (size_t)(ccol + ar1) * DD + k0 + ac1);
        CP_ASYNC16(sb_lo + (uint32_t)(ar0 * SPITCH + ac0) * 2,
                   g_wt_lo + (size_t)(ccol + ar0) * DD + k0 + ac0);
        CP_ASYNC16(sb_lo + (uint32_t)(ar1 * SPITCH + ac1) * 2,
                   g_wt_lo + (size_t)(ccol + ar1) * DD + k0 + ac1);
    };

    load_tile(0);
    CP_COMMIT();

    for (int it = 0; it < DD / 32; ++it) {
        CP_WAIT0();
        __syncthreads();

        // stage all fragments to registers
        uint32_t ah[2][4][4], al[2][4][4], bh[2][2][4], bl[2][2][4];
#pragma unroll
        for (int kk2 = 0; kk2 < 2; ++kk2) {
            const int kk = kk2 * 16;
#pragma unroll
            for (int mt = 0; mt < 4; ++mt) {
                int row = wm * 64 + mt * 16 + lrow;
                uint32_t boff = (uint32_t)(row * SPITCH + kk + lcol8) * 2;
                LDSM_X4(ah[kk2][mt], sa_hi + boff);
                LDSM_X4(al[kk2][mt], sa_lo + boff);
            }
#pragma unroll
            for (int nb = 0; nb < 2; ++nb) {
                int row = wn * 32 + nb * 16 + lrow;
                uint32_t boff = (uint32_t)(row * SPITCH + kk + lcol8) * 2;
                LDSM_X4(bh[kk2][nb], sb_hi + boff);
                LDSM_X4(bl[kk2][nb], sb_lo + boff);
            }
        }
        __syncthreads();

        if (it + 1 < DD / 32) {
            load_tile(it + 1);
            CP_COMMIT();
        }

#pragma unroll
        for (int kk2 = 0; kk2 < 2; ++kk2) {
#pragma unroll
            for (int mt = 0; mt < 4; ++mt) {
#pragma unroll
                for (int nt = 0; nt < 4; ++nt) {
                    int nb = nt >> 1;
                    int hh = nt & 1;
                    uint32_t b0h = bh[kk2][nb][hh], b1h = bh[kk2][nb][2 + hh];
                    uint32_t b0l = bl[kk2][nb][hh], b1l = bl[kk2][nb][2 + hh];
                    MMA_BF16(acc[mt][nt], ah[kk2][mt], b0h, b1h);
                    MMA_BF16(acc[mt][nt], ah[kk2][mt], b0l, b1l);
                    MMA_BF16(acc[mt][nt], al[kk2][mt], b0h, b1h);
                }
            }
        }
    }

    // ---- epilogue: fp16 h2 write + fused score dots ----
    const int tq = lane >> 2;
    const int tr = lane & 3;
    float psrc[4][2] = {{0.f, 0.f}, {0.f, 0.f}, {0.f, 0.f}, {0.f, 0.f}};
    float pdst[4][2] = {{0.f, 0.f}, {0.f, 0.f}, {0.f, 0.f}, {0.f, 0.f}};

#pragma unroll
    for (int mt = 0; mt < 4; ++mt) {
#pragma unroll
        for (int nt = 0; nt < 4; ++nt) {
            int colc = wn * 32 + nt * 8 + tr * 2;
            float a0 = s_av[colc], a1 = s_av[colc + 1];
            float b0 = s_av2[colc], b1 = s_av2[colc + 1];
            psrc[mt][0] += acc[mt][nt][0] * a0 + acc[mt][nt][1] * a1;
            pdst[mt][0] += acc[mt][nt][0] * b0 + acc[mt][nt][1] * b1;
            psrc[mt][1] += acc[mt][nt][2] * a0 + acc[mt][nt][3] * a1;
            pdst[mt][1] += acc[mt][nt][2] * b0 + acc[mt][nt][3] * b1;

            int row0 = crow + wm * 64 + mt * 16 + tq;
            int col = ccol + colc;
            if (row0 < M)
                *(__half2*)(Ch + (size_t)row0 * DD + col) =
                    __floats2half2_rn(acc[mt][nt][0], acc[mt][nt][1]);
            int row1 = row0 + 8;
            if (row1 < M)
                *(__half2*)(Ch + (size_t)row1 * DD + col) =
                    __floats2half2_rn(acc[mt][nt][2], acc[mt][nt][3]);
        }
    }

    // reduce partial dots across the 4 lanes of each quad (tr)
#pragma unroll
    for (int off = 1; off <= 2; off <<= 1) {
#pragma unroll
        for (int mt = 0; mt < 4; ++mt)
#pragma unroll
            for (int j = 0; j < 2; ++j) {
                psrc[mt][j] += __shfl_xor_sync(0xffffffffu, psrc[mt][j], off);
                pdst[mt][j] += __shfl_xor_sync(0xffffffffu, pdst[mt][j], off);
            }
    }
    if (tr == 0) {
#pragma unroll
        for (int mt = 0; mt < 4; ++mt)
#pragma unroll
            for (int j = 0; j < 2; ++j) {
                int row = crow + wm * 64 + mt * 16 + tq + j * 8;
                if (row < M) {
                    atomicAdd(&g_ssrc[row], psrc[mt][j]);
                    atomicAdd(&g_sdst[row], pdst[mt][j]);
                }
            }
    }
}

// ======================= aggregation: one warp per node, fp16 rows =======================
template <bool SPLIT_OUT>
__global__ __launch_bounds__(256)
void aggregate_kernel(const __half* __restrict__ h2h, float* __restrict__ out, int N) {
    int warp = (blockIdx.x * blockDim.x + threadIdx.x) >> 5;
    if (warp >= N) return;
    int lane = threadIdx.x & 31;

    float acc[8] = {0.f, 0.f, 0.f, 0.f, 0.f, 0.f, 0.f, 0.f};
    float dsum = 0.f;
    float ss = g_ssrc[warp];

    int beg = g_rowptr[warp];
    int end = g_rowptr[warp + 1];
#pragma unroll 4
    for (int i = beg; i < end; ++i) {
        int d = g_edst[i];
        float sc = ss + g_sdst[d];
        float l = sc > 0.f ? sc : NEG_SLOPE * sc;
        float e = __expf(-l);
        dsum += e;
        uint4 v = *((const uint4*)(h2h + (size_t)d * DD) + lane);
        float2 f0 = __half22float2(*reinterpret_cast<__half2*>(&v.x));
        float2 f1 = __half22float2(*reinterpret_cast<__half2*>(&v.y));
        float2 f2 = __half22float2(*reinterpret_cast<__half2*>(&v.z));
        float2 f3 = __half22float2(*reinterpret_cast<__half2*>(&v.w));
        acc[0] += e * f0.x; acc[1] += e * f0.y;
        acc[2] += e * f1.x; acc[3] += e * f1.y;
        acc[4] += e * f2.x; acc[5] += e * f2.y;
        acc[6] += e * f3.x; acc[7] += e * f3.y;
    }
    float inv = 1.f / dsum;
    float r[8];
#pragma unroll
    for (int j = 0; j < 8; ++j) {
        float t = acc[j] * inv;
        r[j] = t > 0.f ? t : (__expf(t) - 1.f);
    }
    if (SPLIT_OUT) {
        // write bf16 hi/lo directly (next layer's GEMM input)
        __nv_bfloat16 hi[8], lo[8];
#pragma unroll
        for (int j = 0; j < 8; ++j) {
            hi[j] = __float2bfloat16_rn(r[j]);
            lo[j] = __float2bfloat16_rn(r[j] - __bfloat162float(hi[j]));
        }
        uint4 hv = make_uint4(bf2pack(hi[0], hi[1]), bf2pack(hi[2], hi[3]),
                              bf2pack(hi[4], hi[5]), bf2pack(hi[6], hi[7]));
        uint4 lv = make_uint4(bf2pack(lo[0], lo[1]), bf2pack(lo[2], lo[3]),
                              bf2pack(lo[4], lo[5]), bf2pack(lo[6], lo[7]));
        *((uint4*)(g_ah + (size_t)warp * DD) + lane) = hv;
        *((uint4*)(g_al + (size_t)warp * DD) + lane) = lv;
    } else {
        float4* op = (float4*)(out + (size_t)warp * DD + lane * 8);
        op[0] = make_float4(r[0], r[1], r[2], r[3]);
        op[1] = make_float4(r[4], r[5], r[6], r[7]);
    }
}

// ======================= launch =======================
extern "C" void kernel_launch(void* const* d_in, const int* in_sizes, int n_in,
                              void* d_out, int out_size) {
    const float* emb = (const float*)d_in[0];
    const float* W1  = (const float*)d_in[1];
    const float* a1  = (const float*)d_in[2];
    const float* W2  = (const float*)d_in[3];
    const float* a2  = (const float*)d_in[4];
    const int* edges = (const int*)d_in[5];

    int N = in_sizes[0] / DD;
    int E = in_sizes[5] / 2;
    const int* src = edges;
    const int* dst = edges + E;

    // device addresses of __device__ symbols (host-side g_* names are shadows!)
    __half* h2h = nullptr;
    __nv_bfloat16* ah = nullptr;
    __nv_bfloat16* al = nullptr;
    cudaGetSymbolAddress((void**)&h2h, g_h2h);
    cudaGetSymbolAddress((void**)&ah, g_ah);
    cudaGetSymbolAddress((void**)&al, g_al);

    // CSR build (shared by both layers)
    zero_cnt_kernel<<<(N + 256) / 256, 256>>>(N);
    hist_kernel<<<(E + 255) / 256, 256>>>(src, E);
    scan_kernel<<<1, 1024>>>(N, E);
    scatter_kernel<<<(E + 255) / 256, 256>>>(src, dst, E);

    dim3 ggrid(DD / 128, (N + 127) / 128);
    int agg_blocks = (N * 32 + 255) / 256;

    // layer 1
    split_a_kernel<<<(N * DD / 4 + 255) / 256, 256>>>(emb, N * DD / 4);
    split_w_kernel<<<(DD * DD + 255) / 256, 256>>>(W1);
    zero_s_kernel<<<(N + 255) / 256, 256>>>(N);
    gemm_mma_kernel<<<ggrid, 256>>>(ah, al, a1, h2h, N);
    aggregate_kernel<true><<<agg_blocks, 256>>>(h2h, nullptr, N);

    // layer 2
    split_w_kernel<<<(DD * DD + 255) / 256, 256>>>(W2);
    zero_s_kernel<<<(N + 255) / 256, 256>>>(N);
    gemm_mma_kernel<<<ggrid, 256>>>(ah, al, a2, h2h, N);
    aggregate_kernel<false><<<agg_blocks, 256>>>(h2h, (float*)d_out, N);
}

// round 13
// speedup vs baseline: 2.0123x; 1.2189x over previous
#include <cuda_runtime.h>
#include <cuda_bf16.h>
#include <cuda_fp16.h>
#include <cstdint>

#define DD 256
#define N_MAX 100000
#define E_MAX 3300000
#define NEG_SLOPE 0.2f

// ======================= device scratch =======================
__device__ __half g_h2h[(size_t)N_MAX * DD];          // fp16 h2 for aggregation
__device__ __nv_bfloat16 g_ah[(size_t)N_MAX * DD];    // A hi (gemm input)
__device__ __nv_bfloat16 g_al[(size_t)N_MAX * DD];    // A lo
__device__ float g_ssrc[N_MAX];
__device__ float g_sdst[N_MAX];
__device__ int   g_rowptr[N_MAX + 1];
__device__ int   g_cnt[N_MAX + 1];
__device__ int   g_edst[E_MAX];
__device__ __nv_bfloat16 g_wt_hi1[DD * DD];   // W1^T hi [n][k]
__device__ __nv_bfloat16 g_wt_lo1[DD * DD];
__device__ __nv_bfloat16 g_wt_hi2[DD * DD];   // W2^T hi [n][k]
__device__ __nv_bfloat16 g_wt_lo2[DD * DD];

// ======================= helpers =======================
__device__ __forceinline__ uint32_t smem_u32(const void* p) {
    uint32_t a;
    asm("{ .reg .u64 t; cvta.to.shared.u64 t, %1; cvt.u32.u64 %0, t; }"
        : "=r"(a) : "l"(p));
    return a;
}

__device__ __forceinline__ uint32_t bf2pack(__nv_bfloat16 a, __nv_bfloat16 b) {
    __nv_bfloat162 t(a, b);
    return *reinterpret_cast<uint32_t*>(&t);
}

#define LDSM_X4(r, addr) \
    asm volatile("ldmatrix.sync.aligned.m8n8.x4.shared.b16 {%0,%1,%2,%3}, [%4];" \
        : "=r"((r)[0]), "=r"((r)[1]), "=r"((r)[2]), "=r"((r)[3]) : "r"(addr))

#define MMA_BF16(d, a, b0, b1) \
    asm volatile("mma.sync.aligned.m16n8k16.row.col.f32.bf16.bf16.f32 " \
        "{%0,%1,%2,%3},{%4,%5,%6,%7},{%8,%9},{%0,%1,%2,%3};" \
        : "+f"((d)[0]), "+f"((d)[1]), "+f"((d)[2]), "+f"((d)[3]) \
        : "r"((a)[0]), "r"((a)[1]), "r"((a)[2]), "r"((a)[3]), "r"(b0), "r"(b1))

#define CP_ASYNC16(dst_u32, src_ptr) \
    asm volatile("cp.async.cg.shared.global [%0], [%1], 16;" \
        :: "r"(dst_u32), "l"(src_ptr))
#define CP_COMMIT() asm volatile("cp.async.commit_group;" ::: "memory")
#define CP_WAIT0() asm volatile("cp.async.wait_group 0;" ::: "memory")

// ======================= CSR build =======================
__global__ void zero_cnt_kernel(int n) {
    int i = blockIdx.x * blockDim.x + threadIdx.x;
    if (i <= n) g_cnt[i] = 0;
}

__global__ void hist_kernel(const int* __restrict__ src, int E) {
    int i = blockIdx.x * blockDim.x + threadIdx.x;
    if (i < E) atomicAdd(&g_cnt[src[i]], 1);
}

__global__ void scan_kernel(int N, int E) {
    __shared__ int sums[1024];
    int t = threadIdx.x;
    int C = (N + 1023) / 1024;
    int beg = t * C;
    int end = min(beg + C, N);
    int s = 0;
    for (int i = beg; i < end; ++i) s += g_cnt[i];
    sums[t] = s;
    __syncthreads();
    for (int off = 1; off < 1024; off <<= 1) {
        int v = (t >= off) ? sums[t - off] : 0;
        __syncthreads();
        sums[t] += v;
        __syncthreads();
    }
    int run = (t == 0) ? 0 : sums[t - 1];
    for (int i = beg; i < end; ++i) {
        int c = g_cnt[i];
        g_rowptr[i] = run;
        g_cnt[i] = run;
        run += c;
    }
    if (t == 1023) g_rowptr[N] = E;
}

__global__ void scatter_kernel(const int* __restrict__ src,
                               const int* __restrict__ dst, int E) {
    int i = blockIdx.x * blockDim.x + threadIdx.x;
    if (i < E) {
        int s = src[i];
        int p = atomicAdd(&g_cnt[s], 1);
        g_edst[p] = dst[i];
    }
}

// ======================= operand prep =======================
__global__ void split_w_kernel(const float* __restrict__ W,
                               __nv_bfloat16* __restrict__ wt_hi,
                               __nv_bfloat16* __restrict__ wt_lo) {
    int idx = blockIdx.x * blockDim.x + threadIdx.x;
    if (idx >= DD * DD) return;
    int k = idx >> 8;
    int n = idx & 255;
    float v = W[k * DD + n];
    __nv_bfloat16 h = __float2bfloat16_rn(v);
    __nv_bfloat16 l = __float2bfloat16_rn(v - __bfloat162float(h));
    wt_hi[n * DD + k] = h;
    wt_lo[n * DD + k] = l;
}

__global__ void split_a_kernel(const float* __restrict__ X, int nq) {
    int i = blockIdx.x * blockDim.x + threadIdx.x;   // float4 index
    if (i >= nq) return;
    float4 v = ((const float4*)X)[i];
    __nv_bfloat16 hx = __float2bfloat16_rn(v.x);
    __nv_bfloat16 hy = __float2bfloat16_rn(v.y);
    __nv_bfloat16 hz = __float2bfloat16_rn(v.z);
    __nv_bfloat16 hw = __float2bfloat16_rn(v.w);
    uint2 h = make_uint2(bf2pack(hx, hy), bf2pack(hz, hw));
    uint2 l = make_uint2(
        bf2pack(__float2bfloat16_rn(v.x - __bfloat162float(hx)),
                __float2bfloat16_rn(v.y - __bfloat162float(hy))),
        bf2pack(__float2bfloat16_rn(v.z - __bfloat162float(hz)),
                __float2bfloat16_rn(v.w - __bfloat162float(hw))));
    ((uint2*)g_ah)[i] = h;
    ((uint2*)g_al)[i] = l;
}

__global__ void zero_s_kernel(int N) {
    int i = blockIdx.x * blockDim.x + threadIdx.x;
    if (i < N) {
        g_ssrc[i] = 0.f;
        g_sdst[i] = 0.f;
    }
}

// ======================= bf16x3 mma.sync GEMM + fused dots =======================
#define SPITCH 40   // bf16 elems per smem row (80B) -> conflict-free ldmatrix

__global__ __launch_bounds__(256, 1)
void gemm_mma_kernel(const __nv_bfloat16* __restrict__ Ahi,
                     const __nv_bfloat16* __restrict__ Alo,
                     const __nv_bfloat16* __restrict__ Whi,
                     const __nv_bfloat16* __restrict__ Wlo,
                     const float* __restrict__ avec,
                     __half* __restrict__ Ch, int M) {
    __shared__ __nv_bfloat16 sA_hi[128 * SPITCH];
    __shared__ __nv_bfloat16 sA_lo[128 * SPITCH];
    __shared__ __nv_bfloat16 sB_hi[128 * SPITCH];
    __shared__ __nv_bfloat16 sB_lo[128 * SPITCH];
    __shared__ float s_av[128], s_av2[128];

    const int tid = threadIdx.x;
    const int wid = tid >> 5;
    const int lane = tid & 31;
    const int wm = wid >> 2;
    const int wn = wid & 3;
    const int crow = blockIdx.y * 128;
    const int ccol = blockIdx.x * 128;

    const uint32_t sa_hi = smem_u32(sA_hi);
    const uint32_t sa_lo = smem_u32(sA_lo);
    const uint32_t sb_hi = smem_u32(sB_hi);
    const uint32_t sb_lo = smem_u32(sB_lo);

    if (tid < 128) {
        s_av[tid] = avec[ccol + tid];
        s_av2[tid] = avec[DD + ccol + tid];
    }

    float acc[4][4][4];
#pragma unroll
    for (int i = 0; i < 4; ++i)
#pragma unroll
        for (int j = 0; j < 4; ++j)
#pragma unroll
            for (int k = 0; k < 4; ++k) acc[i][j][k] = 0.f;

    const int lrow = lane & 15;
    const int lcol8 = (lane >> 4) << 3;

    const int slot0 = tid, slot1 = tid + 256;
    const int ar0 = slot0 >> 2, ac0 = (slot0 & 3) * 8;
    const int ar1 = slot1 >> 2, ac1 = (slot1 & 3) * 8;
    const int agr0 = min(crow + ar0, M - 1);
    const int agr1 = min(crow + ar1, M - 1);

    auto load_tile = [&](int it) {
        const int k0 = it * 32;
        CP_ASYNC16(sa_hi + (uint32_t)(ar0 * SPITCH + ac0) * 2,
                   Ahi + (size_t)agr0 * DD + k0 + ac0);
        CP_ASYNC16(sa_hi + (uint32_t)(ar1 * SPITCH + ac1) * 2,
                   Ahi + (size_t)agr1 * DD + k0 + ac1);
        CP_ASYNC16(sa_lo + (uint32_t)(ar0 * SPITCH + ac0) * 2,
                   Alo + (size_t)agr0 * DD + k0 + ac0);
        CP_ASYNC16(sa_lo + (uint32_t)(ar1 * SPITCH + ac1) * 2,
                   Alo + (size_t)agr1 * DD + k0 + ac1);
        CP_ASYNC16(sb_hi + (uint32_t)(ar0 * SPITCH + ac0) * 2,
                   Whi + (size_t)(ccol + ar0) * DD + k0 + ac0);
        CP_ASYNC16(sb_hi + (uint32_t)(ar1 * SPITCH + ac1) * 2,
                   Whi + (size_t)(ccol + ar1) * DD + k0 + ac1);
        CP_ASYNC16(sb_lo + (uint32_t)(ar0 * SPITCH + ac0) * 2,
                   Wlo + (size_t)(ccol + ar0) * DD + k0 + ac0);
        CP_ASYNC16(sb_lo + (uint32_t)(ar1 * SPITCH + ac1) * 2,
                   Wlo + (size_t)(ccol + ar1) * DD + k0 + ac1);
    };

    load_tile(0);
    CP_COMMIT();

    for (int it = 0; it < DD / 32; ++it) {
        CP_WAIT0();
        __syncthreads();

        uint32_t ah[2][4][4], al[2][4][4], bh[2][2][4], bl[2][2][4];
#pragma unroll
        for (int kk2 = 0; kk2 < 2; ++kk2) {
            const int kk = kk2 * 16;
#pragma unroll
            for (int mt = 0; mt < 4; ++mt) {
                int row = wm * 64 + mt * 16 + lrow;
                uint32_t boff = (uint32_t)(row * SPITCH + kk + lcol8) * 2;
                LDSM_X4(ah[kk2][mt], sa_hi + boff);
                LDSM_X4(al[kk2][mt], sa_lo + boff);
            }
#pragma unroll
            for (int nb = 0; nb < 2; ++nb) {
                int row = wn * 32 + nb * 16 + lrow;
                uint32_t boff = (uint32_t)(row * SPITCH + kk + lcol8) * 2;
                LDSM_X4(bh[kk2][nb], sb_hi + boff);
                LDSM_X4(bl[kk2][nb], sb_lo + boff);
            }
        }
        __syncthreads();

        if (it + 1 < DD / 32) {
            load_tile(it + 1);
            CP_COMMIT();
        }

#pragma unroll
        for (int kk2 = 0; kk2 < 2; ++kk2) {
#pragma unroll
            for (int mt = 0; mt < 4; ++mt) {
#pragma unroll
                for (int nt = 0; nt < 4; ++nt) {
                    int nb = nt >> 1;
                    int hh = nt & 1;
                    uint32_t b0h = bh[kk2][nb][hh], b1h = bh[kk2][nb][2 + hh];
                    uint32_t b0l = bl[kk2][nb][hh], b1l = bl[kk2][nb][2 + hh];
                    MMA_BF16(acc[mt][nt], ah[kk2][mt], b0h, b1h);
                    MMA_BF16(acc[mt][nt], ah[kk2][mt], b0l, b1l);
                    MMA_BF16(acc[mt][nt], al[kk2][mt], b0h, b1h);
                }
            }
        }
    }

    // ---- epilogue: fp16 h2 write + fused score dots ----
    const int tq = lane >> 2;
    const int tr = lane & 3;
    float psrc[4][2] = {{0.f, 0.f}, {0.f, 0.f}, {0.f, 0.f}, {0.f, 0.f}};
    float pdst[4][2] = {{0.f, 0.f}, {0.f, 0.f}, {0.f, 0.f}, {0.f, 0.f}};

#pragma unroll
    for (int mt = 0; mt < 4; ++mt) {
#pragma unroll
        for (int nt = 0; nt < 4; ++nt) {
            int colc = wn * 32 + nt * 8 + tr * 2;
            float a0 = s_av[colc], a1 = s_av[colc + 1];
            float b0 = s_av2[colc], b1 = s_av2[colc + 1];
            psrc[mt][0] += acc[mt][nt][0] * a0 + acc[mt][nt][1] * a1;
            pdst[mt][0] += acc[mt][nt][0] * b0 + acc[mt][nt][1] * b1;
            psrc[mt][1] += acc[mt][nt][2] * a0 + acc[mt][nt][3] * a1;
            pdst[mt][1] += acc[mt][nt][2] * b0 + acc[mt][nt][3] * b1;

            int row0 = crow + wm * 64 + mt * 16 + tq;
            int col = ccol + colc;
            if (row0 < M)
                *(__half2*)(Ch + (size_t)row0 * DD + col) =
                    __floats2half2_rn(acc[mt][nt][0], acc[mt][nt][1]);
            int row1 = row0 + 8;
            if (row1 < M)
                *(__half2*)(Ch + (size_t)row1 * DD + col) =
                    __floats2half2_rn(acc[mt][nt][2], acc[mt][nt][3]);
        }
    }

#pragma unroll
    for (int off = 1; off <= 2; off <<= 1) {
#pragma unroll
        for (int mt = 0; mt < 4; ++mt)
#pragma unroll
            for (int j = 0; j < 2; ++j) {
                psrc[mt][j] += __shfl_xor_sync(0xffffffffu, psrc[mt][j], off);
                pdst[mt][j] += __shfl_xor_sync(0xffffffffu, pdst[mt][j], off);
            }
    }
    if (tr == 0) {
#pragma unroll
        for (int mt = 0; mt < 4; ++mt)
#pragma unroll
            for (int j = 0; j < 2; ++j) {
                int row = crow + wm * 64 + mt * 16 + tq + j * 8;
                if (row < M) {
                    atomicAdd(&g_ssrc[row], psrc[mt][j]);
                    atomicAdd(&g_sdst[row], pdst[mt][j]);
                }
            }
    }
}

// ======================= aggregation: one warp per node, fp16 rows =======================
template <bool SPLIT_OUT>
__global__ __launch_bounds__(256)
void aggregate_kernel(const __half* __restrict__ h2h, float* __restrict__ out, int N) {
    int warp = (blockIdx.x * blockDim.x + threadIdx.x) >> 5;
    if (warp >= N) return;
    int lane = threadIdx.x & 31;

    float acc[8] = {0.f, 0.f, 0.f, 0.f, 0.f, 0.f, 0.f, 0.f};
    float dsum = 0.f;
    float ss = g_ssrc[warp];

    int beg = g_rowptr[warp];
    int end = g_rowptr[warp + 1];
#pragma unroll 4
    for (int i = beg; i < end; ++i) {
        int d = g_edst[i];
        float sc = ss + g_sdst[d];
        float l = sc > 0.f ? sc : NEG_SLOPE * sc;
        float e = __expf(-l);
        dsum += e;
        uint4 v = *((const uint4*)(h2h + (size_t)d * DD) + lane);
        float2 f0 = __half22float2(*reinterpret_cast<__half2*>(&v.x));
        float2 f1 = __half22float2(*reinterpret_cast<__half2*>(&v.y));
        float2 f2 = __half22float2(*reinterpret_cast<__half2*>(&v.z));
        float2 f3 = __half22float2(*reinterpret_cast<__half2*>(&v.w));
        acc[0] += e * f0.x; acc[1] += e * f0.y;
        acc[2] += e * f1.x; acc[3] += e * f1.y;
        acc[4] += e * f2.x; acc[5] += e * f2.y;
        acc[6] += e * f3.x; acc[7] += e * f3.y;
    }
    float inv = 1.f / dsum;
    float r[8];
#pragma unroll
    for (int j = 0; j < 8; ++j) {
        float t = acc[j] * inv;
        r[j] = t > 0.f ? t : (__expf(t) - 1.f);
    }
    if (SPLIT_OUT) {
        __nv_bfloat16 hi[8], lo[8];
#pragma unroll
        for (int j = 0; j < 8; ++j) {
            hi[j] = __float2bfloat16_rn(r[j]);
            lo[j] = __float2bfloat16_rn(r[j] - __bfloat162float(hi[j]));
        }
        uint4 hv = make_uint4(bf2pack(hi[0], hi[1]), bf2pack(hi[2], hi[3]),
                              bf2pack(hi[4], hi[5]), bf2pack(hi[6], hi[7]));
        uint4 lv = make_uint4(bf2pack(lo[0], lo[1]), bf2pack(lo[2], lo[3]),
                              bf2pack(lo[4], lo[5]), bf2pack(lo[6], lo[7]));
        *((uint4*)(g_ah + (size_t)warp * DD) + lane) = hv;
        *((uint4*)(g_al + (size_t)warp * DD) + lane) = lv;
    } else {
        float4* op = (float4*)(out + (size_t)warp * DD + lane * 8);
        op[0] = make_float4(r[0], r[1], r[2], r[3]);
        op[1] = make_float4(r[4], r[5], r[6], r[7]);
    }
}

// ======================= launch =======================
extern "C" void kernel_launch(void* const* d_in, const int* in_sizes, int n_in,
                              void* d_out, int out_size) {
    const float* emb = (const float*)d_in[0];
    const float* W1  = (const float*)d_in[1];
    const float* a1  = (const float*)d_in[2];
    const float* W2  = (const float*)d_in[3];
    const float* a2  = (const float*)d_in[4];
    const int* edges = (const int*)d_in[5];

    int N = in_sizes[0] / DD;
    int E = in_sizes[5] / 2;
    const int* src = edges;
    const int* dst = edges + E;

    // device addresses of __device__ symbols
    __half* h2h = nullptr;
    __nv_bfloat16 *ah = nullptr, *al = nullptr;
    __nv_bfloat16 *wh1 = nullptr, *wl1 = nullptr, *wh2 = nullptr, *wl2 = nullptr;
    cudaGetSymbolAddress((void**)&h2h, g_h2h);
    cudaGetSymbolAddress((void**)&ah, g_ah);
    cudaGetSymbolAddress((void**)&al, g_al);
    cudaGetSymbolAddress((void**)&wh1, g_wt_hi1);
    cudaGetSymbolAddress((void**)&wl1, g_wt_lo1);
    cudaGetSymbolAddress((void**)&wh2, g_wt_hi2);
    cudaGetSymbolAddress((void**)&wl2, g_wt_lo2);

    // lazy-created side stream + fork/join events (created on the first,
    // uncaptured correctness call; reused identically on every call)
    static cudaStream_t s_side = nullptr;
    static cudaEvent_t ev_fork = nullptr, ev_join = nullptr;
    if (!s_side) {
        cudaStreamCreateWithFlags(&s_side, cudaStreamNonBlocking);
        cudaEventCreateWithFlags(&ev_fork, cudaEventDisableTiming);
        cudaEventCreateWithFlags(&ev_join, cudaEventDisableTiming);
    }

    dim3 ggrid(DD / 128, (N + 127) / 128);
    int agg_blocks = (N * 32 + 255) / 256;

    // ---- fork: CSR build on side stream ----
    cudaEventRecord(ev_fork, 0);
    cudaStreamWaitEvent(s_side, ev_fork, 0);
    zero_cnt_kernel<<<(N + 256) / 256, 256, 0, s_side>>>(N);
    hist_kernel<<<(E + 255) / 256, 256, 0, s_side>>>(src, E);
    scan_kernel<<<1, 1024, 0, s_side>>>(N, E);
    scatter_kernel<<<(E + 255) / 256, 256, 0, s_side>>>(src, dst, E);
    cudaEventRecord(ev_join, s_side);

    // ---- main stream: layer-1 prep + GEMM (overlaps CSR) ----
    split_a_kernel<<<(N * DD / 4 + 255) / 256, 256>>>(emb, N * DD / 4);
    split_w_kernel<<<(DD * DD + 255) / 256, 256>>>(W1, wh1, wl1);
    split_w_kernel<<<(DD * DD + 255) / 256, 256>>>(W2, wh2, wl2);
    zero_s_kernel<<<(N + 255) / 256, 256>>>(N);
    gemm_mma_kernel<<<ggrid, 256>>>(ah, al, wh1, wl1, a1, h2h, N);

    // ---- join: aggregation needs CSR ----
    cudaStreamWaitEvent(0, ev_join, 0);
    aggregate_kernel<true><<<agg_blocks, 256>>>(h2h, nullptr, N);

    // ---- layer 2 ----
    zero_s_kernel<<<(N + 255) / 256, 256>>>(N);
    gemm_mma_kernel<<<ggrid, 256>>>(ah, al, wh2, wl2, a2, h2h, N);
    aggregate_kernel<false><<<agg_blocks, 256>>>(h2h, (float*)d_out, N);
}